// round 15
// baseline (speedup 1.0000x reference)
#include <cuda_runtime.h>
#include <cuda_fp16.h>
#include <math.h>

#define NN   50000
#define MM   10000
#define NNZT 400000
#define DF   128
#define HIDN 256
#define OUTC 40
#define STEPS 10

#define NBV 196                 // ceil(NN/256) == scan grid
#define NBE 40                  // ceil(MM/256)
#define EB  157                 // ceil(MM/64)  edge-sort blocks
#define NB  391                 // ceil(NN/128) node-sort blocks
#define EGRID  1184             // e2v exact-fit grid (148*8)
#define EWARPS (EGRID * 8)
#define PHIGRID 1024            // phi_node reduction grid

#define H2(x) (*(const __half2*)&(x))

// ---------------- scratch (static device globals; no allocation) ----------------
__device__ int   g_cntV[NN];
__device__ int   g_cntE[MM];
__device__ int   g_rowV[NN + 1];
__device__ int   g_rowE[MM + 1];
__device__ int   g_fillV[NN];
__device__ int   g_fillE[MM];
__device__ int   g_adjV[NNZT];
__device__ int   g_adjE[NNZT];
__device__ float g_invD[NN];
__device__ float g_sD[NN];
__device__ float g_wV[NN];             // sum_{e ∋ v} invDE[e]  (includes 1/16384)
__device__ float g_invDE[MM];          // pre-scaled by 1/16384 (features stored x128)
__device__ __align__(16) __half g_Xh[(size_t)NN * DF];   // 128 * X / sqrtD (fp16)
__device__ __align__(16) __half g_Zn[(size_t)NN * DF];   // 128 * G / sqrtD (fp16)
__device__ __align__(16) __half g_Pe[(size_t)MM * DF];   // V2E(G), unscaled (fp16)
__device__ __align__(16) __half g_W1hT[(size_t)HIDN * DF];   // W1^T fp16
__device__ __align__(16) __half g_W2hT[(size_t)OUTC * HIDN]; // W2^T fp16
__device__ float g_part[2048];
__device__ int   g_arrive;
__device__ float g_invphi[STEPS + 1];
__device__ int   g_scanPartV[256];
__device__ int   g_scanPartE[256];
__device__ int          g_fbarCnt;
__device__ volatile int g_fbarGen;

// ---------------- CSR build ----------------
__global__ void count_kernel(const int* __restrict__ V, const int* __restrict__ E) {
    int i = blockIdx.x * blockDim.x + threadIdx.x;
    if (i >= NNZT) return;
    atomicAdd(&g_cntV[V[i]], 1);
    atomicAdd(&g_cntE[E[i]], 1);
}

// Fused 3-phase scan: block partials -> ONE grid barrier -> rowptr write
// (each block redundantly scans the 196/40 partials). 196 blocks co-resident.
__global__ void __launch_bounds__(256) scan_fused() {
    __shared__ int ss[256];
    __shared__ int sbase;
    int tid = threadIdx.x;
    int b = blockIdx.x;

    // phase 1: block partial sums
    {
        int i = b * 256 + tid;
        ss[tid] = (i < NN) ? g_cntV[i] : 0;
        __syncthreads();
        for (int o = 128; o; o >>= 1) {
            if (tid < o) ss[tid] += ss[tid + o];
            __syncthreads();
        }
        if (tid == 0) g_scanPartV[b] = ss[0];
        __syncthreads();
        if (b < NBE) {
            int j = b * 256 + tid;
            ss[tid] = (j < MM) ? g_cntE[j] : 0;
            __syncthreads();
            for (int o = 128; o; o >>= 1) {
                if (tid < o) ss[tid] += ss[tid + o];
                __syncthreads();
            }
            if (tid == 0) g_scanPartE[b] = ss[0];
            __syncthreads();
        }
    }
    // grid barrier
    __syncthreads();
    if (tid == 0) {
        __threadfence();
        int gen = g_fbarGen;
        if (atomicAdd(&g_fbarCnt, 1) == NBV - 1) {
            g_fbarCnt = 0;
            __threadfence();
            g_fbarGen = gen + 1;
        } else {
            while (g_fbarGen == gen) { __nanosleep(32); }
            __threadfence();
        }
    }
    __syncthreads();
    // phase 2: rowptr write (redundant partial scan per block)
    {
        int x = (tid < NBV) ? __ldcg(&g_scanPartV[tid]) : 0;
        ss[tid] = x;
        __syncthreads();
        for (int o = 1; o < 256; o <<= 1) {
            int u = 0;
            if (tid >= o) u = ss[tid - o];
            __syncthreads();
            ss[tid] += u;
            __syncthreads();
        }
        if (tid == 0) sbase = (b == 0) ? 0 : ss[b - 1];
        __syncthreads();
        int baseV = sbase;
        __syncthreads();
        int i = b * 256 + tid;
        int v = (i < NN) ? g_cntV[i] : 0;
        ss[tid] = v;
        __syncthreads();
        for (int o = 1; o < 256; o <<= 1) {
            int u = 0;
            if (tid >= o) u = ss[tid - o];
            __syncthreads();
            ss[tid] += u;
            __syncthreads();
        }
        if (i < NN) {
            g_rowV[i] = baseV + ss[tid] - v;
            if (i == NN - 1) g_rowV[NN] = baseV + ss[tid];
        }
        __syncthreads();
        if (b < NBE) {
            int x2 = (tid < NBE) ? __ldcg(&g_scanPartE[tid]) : 0;
            ss[tid] = x2;
            __syncthreads();
            for (int o = 1; o < 256; o <<= 1) {
                int u = 0;
                if (tid >= o) u = ss[tid - o];
                __syncthreads();
                ss[tid] += u;
                __syncthreads();
            }
            if (tid == 0) sbase = (b == 0) ? 0 : ss[b - 1];
            __syncthreads();
            int baseE = sbase;
            int j = b * 256 + tid;
            int e = (j < MM) ? g_cntE[j] : 0;
            ss[tid] = e;
            __syncthreads();
            for (int o = 1; o < 256; o <<= 1) {
                int u = 0;
                if (tid >= o) u = ss[tid - o];
                __syncthreads();
                ss[tid] += u;
                __syncthreads();
            }
            if (j < MM) {
                g_rowE[j] = baseE + ss[tid] - e;
                if (j == MM - 1) g_rowE[MM] = baseE + ss[tid];
            }
        }
    }
}

__global__ void fill_kernel(const int* __restrict__ V, const int* __restrict__ E) {
    int i = blockIdx.x * blockDim.x + threadIdx.x;
    if (i >= NNZT) return;
    int v = V[i], e = E[i];
    int pv = g_rowV[v] + atomicAdd(&g_fillV[v], 1);
    g_adjV[pv] = e;
    int pe = g_rowE[e] + atomicAdd(&g_fillE[e], 1);
    g_adjE[pe] = v;
}

// Both segment sorts (edges then nodes) in one launch; insertion sort in smem.
// Node path also computes g_wV (sum of invDE over sorted adjacency, fixed order).
__global__ void sort_both_kernel() {
    __shared__ int buf[8192];
    int t = threadIdx.x;
    if (blockIdx.x < EB) {
        if (t >= 64) return;
        int sgi = blockIdx.x * 64 + t;
        if (sgi >= MM) return;
        int s = g_rowE[sgi], e = g_rowE[sgi + 1];
        int len = e - s;
        if (len <= 1) return;
        if (len <= 128) {
            for (int k = 0; k < len; k++) buf[t + 64 * k] = g_adjE[s + k];
            for (int i = 1; i < len; i++) {
                int key = buf[t + 64 * i];
                int j = i - 1;
                while (j >= 0 && buf[t + 64 * j] > key) {
                    buf[t + 64 * (j + 1)] = buf[t + 64 * j];
                    j--;
                }
                buf[t + 64 * (j + 1)] = key;
            }
            for (int k = 0; k < len; k++) g_adjE[s + k] = buf[t + 64 * k];
        } else {
            for (int i = s + 1; i < e; i++) {
                int key = g_adjE[i];
                int j = i - 1;
                while (j >= s && g_adjE[j] > key) { g_adjE[j + 1] = g_adjE[j]; j--; }
                g_adjE[j + 1] = key;
            }
        }
    } else {
        int sgi = (blockIdx.x - EB) * 128 + t;
        if (sgi >= NN) return;
        int s = g_rowV[sgi], e = g_rowV[sgi + 1];
        int len = e - s;
        float w = 0.f;
        if (len <= 1) {
            if (len == 1) w = __ldg(&g_invDE[g_adjV[s]]);
            g_wV[sgi] = w;
            return;
        }
        if (len <= 48) {
            for (int k = 0; k < len; k++) buf[t + 128 * k] = g_adjV[s + k];
            for (int i = 1; i < len; i++) {
                int key = buf[t + 128 * i];
                int j = i - 1;
                while (j >= 0 && buf[t + 128 * j] > key) {
                    buf[t + 128 * (j + 1)] = buf[t + 128 * j];
                    j--;
                }
                buf[t + 128 * (j + 1)] = key;
            }
            for (int k = 0; k < len; k++) {
                int a = buf[t + 128 * k];
                g_adjV[s + k] = a;
                w += __ldg(&g_invDE[a]);
            }
        } else {
            for (int i = s + 1; i < e; i++) {
                int key = g_adjV[i];
                int j = i - 1;
                while (j >= s && g_adjV[j] > key) { g_adjV[j + 1] = g_adjV[j]; j--; }
                g_adjV[j + 1] = key;
            }
            for (int k = 0; k < len; k++) w += __ldg(&g_invDE[g_adjV[s + k]]);
        }
        g_wV[sgi] = w;
    }
}

// Xh = 128 * X * rsD (fp16); scalars (invDE pre-divided by 16384); W fp16.
__global__ void convert_kernel(const float* __restrict__ X,
                               const float* __restrict__ W1,
                               const float* __restrict__ W2) {
    int i = blockIdx.x * blockDim.x + threadIdx.x;  // over NN*32
    int row = i >> 5;
    float c = (float)__ldg(&g_cntV[row]);
    float r = rsqrtf(c) * 128.0f;
    float4 x = __ldg(&((const float4*)X)[i]);
    __half2 h0 = __floats2half2_rn(x.x * r, x.y * r);
    __half2 h1 = __floats2half2_rn(x.z * r, x.w * r);
    uint2 u;
    u.x = *(unsigned*)&h0;
    u.y = *(unsigned*)&h1;
    ((uint2*)g_Xh)[i] = u;
    if (i < NN) {
        float cv = (float)g_cntV[i];
        g_invD[i] = 1.0f / cv;
        g_sD[i] = sqrtf(cv);
    }
    if (i < MM) {
        g_invDE[i] = 1.0f / (16384.0f * (float)g_cntE[i]);
    }
    if (i < HIDN * DF) {
        int n = i >> 7, k = i & 127;
        g_W1hT[i] = __float2half(__ldg(&W1[k * HIDN + n]));
    }
    if (i < OUTC * HIDN) {
        int n = i >> 8, k = i & 255;
        g_W2hT[i] = __float2half(__ldg(&W2[k * OUTC + n]));
    }
}

// ---------------- diffusion ----------------
__device__ __forceinline__ void acc_sq(float* a, uint4 u) {
    float2 a0 = __half22float2(H2(u.x));
    float2 a1 = __half22float2(H2(u.y));
    float2 a2 = __half22float2(H2(u.z));
    float2 a3 = __half22float2(H2(u.w));
    a[0] += a0.x * a0.x; a[1] += a0.y * a0.y;
    a[2] += a1.x * a1.x; a[3] += a1.y * a1.y;
    a[4] += a2.x * a2.x; a[5] += a2.y * a2.y;
    a[6] += a3.x * a3.x; a[7] += a3.y * a3.y;
}
__device__ __forceinline__ void acc_lin(float* a, uint4 u) {
    float2 a0 = __half22float2(H2(u.x));
    float2 a1 = __half22float2(H2(u.y));
    float2 a2 = __half22float2(H2(u.z));
    float2 a3 = __half22float2(H2(u.w));
    a[0] += a0.x; a[1] += a0.y; a[2] += a1.x; a[3] += a1.y;
    a[4] += a2.x; a[5] += a2.y; a[6] += a3.x; a[7] += a3.y;
}
__device__ __forceinline__ void hacc_sq(__half2& hx, __half2& hy, __half2& hz, __half2& hw,
                                        uint4 u) {
    hx = __hfma2(H2(u.x), H2(u.x), hx);
    hy = __hfma2(H2(u.y), H2(u.y), hy);
    hz = __hfma2(H2(u.z), H2(u.z), hz);
    hw = __hfma2(H2(u.w), H2(u.w), hw);
}
__device__ __forceinline__ void flush4(float* acc, __half2 hx, __half2 hy, __half2 hz, __half2 hw) {
    float2 f;
    f = __half22float2(hx); acc[0] += f.x; acc[1] += f.y;
    f = __half22float2(hy); acc[2] += f.x; acc[3] += f.y;
    f = __half22float2(hz); acc[4] += f.x; acc[5] += f.y;
    f = __half22float2(hw); acc[6] += f.x; acc[7] += f.y;
}

// V2E + phi fused. Warp per hyperedge; half-warps split incidences (stride 2).
// 4-row fp16 blocks, then 2-row fp16 blocks, then fp32 singles. Deterministic.
__global__ void v2e_kernel(const __half* __restrict__ Z, int t) {
    int warp = (blockIdx.x * blockDim.x + threadIdx.x) >> 5;
    int lane = threadIdx.x & 31;
    int half = lane >> 4;
    int fl = lane & 15;
    float ps = 0.f;
    if (warp < MM) {
        int e = warp;
        int s = g_rowE[e], en = g_rowE[e + 1];
        const uint4* Z4 = (const uint4*)Z;
        float acc[8];
#pragma unroll
        for (int k = 0; k < 8; k++) acc[k] = 0.f;
        int j = s + half;
        for (; j + 6 < en; j += 8) {
            int v0 = __ldg(&g_adjE[j]);
            int v1 = __ldg(&g_adjE[j + 2]);
            int v2i = __ldg(&g_adjE[j + 4]);
            int v3 = __ldg(&g_adjE[j + 6]);
            uint4 u0 = __ldg(&Z4[(size_t)v0 * 16 + fl]);
            uint4 u1 = __ldg(&Z4[(size_t)v1 * 16 + fl]);
            uint4 u2 = __ldg(&Z4[(size_t)v2i * 16 + fl]);
            uint4 u3 = __ldg(&Z4[(size_t)v3 * 16 + fl]);
            __half2 hx = __hmul2(H2(u0.x), H2(u0.x));
            __half2 hy = __hmul2(H2(u0.y), H2(u0.y));
            __half2 hz = __hmul2(H2(u0.z), H2(u0.z));
            __half2 hw = __hmul2(H2(u0.w), H2(u0.w));
            hacc_sq(hx, hy, hz, hw, u1);
            hacc_sq(hx, hy, hz, hw, u2);
            hacc_sq(hx, hy, hz, hw, u3);
            flush4(acc, hx, hy, hz, hw);
        }
        for (; j + 2 < en; j += 4) {
            int v0 = __ldg(&g_adjE[j]);
            int v1 = __ldg(&g_adjE[j + 2]);
            uint4 u0 = __ldg(&Z4[(size_t)v0 * 16 + fl]);
            uint4 u1 = __ldg(&Z4[(size_t)v1 * 16 + fl]);
            __half2 hx = __hmul2(H2(u0.x), H2(u0.x));
            __half2 hy = __hmul2(H2(u0.y), H2(u0.y));
            __half2 hz = __hmul2(H2(u0.z), H2(u0.z));
            __half2 hw = __hmul2(H2(u0.w), H2(u0.w));
            hacc_sq(hx, hy, hz, hw, u1);
            flush4(acc, hx, hy, hz, hw);
        }
        for (; j < en; j += 2) {
            int v = __ldg(&g_adjE[j]);
            uint4 u = __ldg(&Z4[(size_t)v * 16 + fl]);
            acc_sq(acc, u);
        }
#pragma unroll
        for (int k = 0; k < 8; k++) acc[k] += __shfl_xor_sync(0xffffffffu, acc[k], 16);
        if (half == 0) {
            float ide = g_invDE[e];
            float v0 = acc[0] * ide, v1 = acc[1] * ide, v2 = acc[2] * ide, v3 = acc[3] * ide;
            float v4 = acc[4] * ide, v5 = acc[5] * ide, v6 = acc[6] * ide, v7 = acc[7] * ide;
            __half2 o0 = __floats2half2_rn(sqrtf(v0), sqrtf(v1));
            __half2 o1 = __floats2half2_rn(sqrtf(v2), sqrtf(v3));
            __half2 o2 = __floats2half2_rn(sqrtf(v4), sqrtf(v5));
            __half2 o3 = __floats2half2_rn(sqrtf(v6), sqrtf(v7));
            uint4 u;
            u.x = *(unsigned*)&o0; u.y = *(unsigned*)&o1;
            u.z = *(unsigned*)&o2; u.w = *(unsigned*)&o3;
            ((uint4*)g_Pe)[(size_t)e * 16 + fl] = u;
            ps = v0 + v1 + v2 + v3 + v4 + v5 + v6 + v7;
        }
    }
#pragma unroll
    for (int o = 16; o; o >>= 1) ps += __shfl_xor_sync(0xffffffffu, ps, o);

    __shared__ float wsum[8];
    __shared__ int lastflag;
    if (lane == 0) wsum[threadIdx.x >> 5] = ps;
    __syncthreads();
    if (threadIdx.x == 0) {
        float b = 0.f;
#pragma unroll
        for (int w = 0; w < 8; w++) b += wsum[w];
        g_part[blockIdx.x] = b;
        __threadfence();
        int old = atomicAdd(&g_arrive, 1);
        lastflag = (old == (int)gridDim.x - 1);
    }
    __syncthreads();
    if (lastflag) {
        __threadfence();
        float sacc = 0.f;
        for (int i = threadIdx.x; i < (int)gridDim.x; i += 256) sacc += g_part[i];
        __shared__ float sr[256];
        sr[threadIdx.x] = sacc;
        __syncthreads();
        for (int o = 128; o; o >>= 1) {
            if (threadIdx.x < o) sr[threadIdx.x] += sr[threadIdx.x + o];
            __syncthreads();
        }
        if (threadIdx.x == 0) {
            g_invphi[t] = 1.0f / (2.0f * sqrtf(sr[0]));
            g_arrive = 0;
        }
    }
}

// E2V + combine. Exact-fit grid (1 wave @8/SM), block-stride over nodes.
__global__ void __launch_bounds__(256) e2v_kernel(int t) {
    int gwarp = (blockIdx.x * blockDim.x + threadIdx.x) >> 5;
    int lane = threadIdx.x & 31;
    int half = lane >> 4;
    int fl = lane & 15;
    float sp = g_invphi[t - 1];
    float s0 = g_invphi[0];
    const uint4* Pe4 = (const uint4*)g_Pe;
    for (int v = gwarp; v < NN; v += EWARPS) {
        int s = g_rowV[v], en = g_rowV[v + 1];
        float acc[8];
#pragma unroll
        for (int k = 0; k < 8; k++) acc[k] = 0.f;
        int j = s + half;
        for (; j + 6 < en; j += 8) {
            int e0 = __ldg(&g_adjV[j]);
            int e1 = __ldg(&g_adjV[j + 2]);
            int e2 = __ldg(&g_adjV[j + 4]);
            int e3 = __ldg(&g_adjV[j + 6]);
            uint4 u0 = __ldg(&Pe4[(size_t)e0 * 16 + fl]);
            uint4 u1 = __ldg(&Pe4[(size_t)e1 * 16 + fl]);
            uint4 u2 = __ldg(&Pe4[(size_t)e2 * 16 + fl]);
            uint4 u3 = __ldg(&Pe4[(size_t)e3 * 16 + fl]);
            __half2 hx = __hadd2(__hadd2(H2(u0.x), H2(u1.x)), __hadd2(H2(u2.x), H2(u3.x)));
            __half2 hy = __hadd2(__hadd2(H2(u0.y), H2(u1.y)), __hadd2(H2(u2.y), H2(u3.y)));
            __half2 hz = __hadd2(__hadd2(H2(u0.z), H2(u1.z)), __hadd2(H2(u2.z), H2(u3.z)));
            __half2 hw = __hadd2(__hadd2(H2(u0.w), H2(u1.w)), __hadd2(H2(u2.w), H2(u3.w)));
            flush4(acc, hx, hy, hz, hw);
        }
        for (; j + 2 < en; j += 4) {
            int e0 = __ldg(&g_adjV[j]);
            int e1 = __ldg(&g_adjV[j + 2]);
            uint4 u0 = __ldg(&Pe4[(size_t)e0 * 16 + fl]);
            uint4 u1 = __ldg(&Pe4[(size_t)e1 * 16 + fl]);
            __half2 hx = __hadd2(H2(u0.x), H2(u1.x));
            __half2 hy = __hadd2(H2(u0.y), H2(u1.y));
            __half2 hz = __hadd2(H2(u0.z), H2(u1.z));
            __half2 hw = __hadd2(H2(u0.w), H2(u1.w));
            flush4(acc, hx, hy, hz, hw);
        }
        for (; j < en; j += 2) {
            int e = __ldg(&g_adjV[j]);
            uint4 u = __ldg(&Pe4[(size_t)e * 16 + fl]);
            acc_lin(acc, u);
        }
#pragma unroll
        for (int k = 0; k < 8; k++) acc[k] += __shfl_xor_sync(0xffffffffu, acc[k], 16);
        if (half == 0) {
            float a = 115.2f * sp * g_invD[v];
            float b = 0.1f * s0;
            uint4 ux = __ldg(&((const uint4*)g_Xh)[(size_t)v * 16 + fl]);
            float2 x0 = __half22float2(H2(ux.x));
            float2 x1 = __half22float2(H2(ux.y));
            float2 x2 = __half22float2(H2(ux.z));
            float2 x3 = __half22float2(H2(ux.w));
            __half2 o0 = __floats2half2_rn(a * acc[0] + b * x0.x, a * acc[1] + b * x0.y);
            __half2 o1 = __floats2half2_rn(a * acc[2] + b * x1.x, a * acc[3] + b * x1.y);
            __half2 o2 = __floats2half2_rn(a * acc[4] + b * x2.x, a * acc[5] + b * x2.y);
            __half2 o3 = __floats2half2_rn(a * acc[6] + b * x3.x, a * acc[7] + b * x3.y);
            uint4 u;
            u.x = *(unsigned*)&o0; u.y = *(unsigned*)&o1;
            u.z = *(unsigned*)&o2; u.w = *(unsigned*)&o3;
            ((uint4*)g_Zn)[(size_t)v * 16 + fl] = u;
        }
    }
}

// Final phi via node identity: S = sum_v w_v * ||Zn_v||^2 (w includes 1/16384).
__global__ void __launch_bounds__(256) phi_node_kernel(int t) {
    const uint2* Z2 = (const uint2*)g_Zn;
    int tid = threadIdx.x;
    int stride = PHIGRID * 256;
    float s = 0.f;
    for (int i = blockIdx.x * 256 + tid; i < NN * 32; i += stride) {
        float w = __ldg(&g_wV[i >> 5]);
        uint2 u = __ldg(&Z2[i]);
        float2 a0 = __half22float2(H2(u.x));
        float2 a1 = __half22float2(H2(u.y));
        s += w * (a0.x * a0.x + a0.y * a0.y + a1.x * a1.x + a1.y * a1.y);
    }
    __shared__ float sr[256];
    __shared__ int lastflag;
    sr[tid] = s;
    __syncthreads();
    for (int o = 128; o; o >>= 1) {
        if (tid < o) sr[tid] += sr[tid + o];
        __syncthreads();
    }
    if (tid == 0) {
        g_part[blockIdx.x] = sr[0];
        __threadfence();
        int old = atomicAdd(&g_arrive, 1);
        lastflag = (old == PHIGRID - 1);
    }
    __syncthreads();
    if (lastflag) {
        __threadfence();
        float sacc = 0.f;
        for (int i = tid; i < PHIGRID; i += 256) sacc += g_part[i];
        sr[tid] = sacc;
        __syncthreads();
        for (int o = 128; o; o >>= 1) {
            if (tid < o) sr[tid] += sr[tid + o];
            __syncthreads();
        }
        if (tid == 0) {
            g_invphi[t] = 1.0f / (2.0f * sqrtf(sr[0]));
            g_arrive = 0;
        }
    }
}

// ---------------- tensor-core decoder ----------------
__device__ __forceinline__ void mma16816(float* c, unsigned a0, unsigned a1, unsigned a2,
                                         unsigned a3, unsigned b0, unsigned b1) {
    asm volatile(
        "mma.sync.aligned.m16n8k16.row.col.f32.f16.f16.f32 "
        "{%0,%1,%2,%3}, {%4,%5,%6,%7}, {%8,%9}, {%0,%1,%2,%3};"
        : "+f"(c[0]), "+f"(c[1]), "+f"(c[2]), "+f"(c[3])
        : "r"(a0), "r"(a1), "r"(a2), "r"(a3), "r"(b0), "r"(b1));
}

#define DPAD 264
__global__ void decoder_kernel(const float* __restrict__ b1v, const float* __restrict__ gammav,
                               const float* __restrict__ betav, const float* __restrict__ b2v,
                               float* __restrict__ out) {
    __shared__ __half hs[64 * DPAD];
    __shared__ float red_s[2][64];
    __shared__ float red_q[2][64];

    int tid = threadIdx.x;

    // re-zero CSR counters for the next graph replay (first run: static zero-init)
    {
        int gtid = blockIdx.x * 256 + tid;
        if (gtid < NN) { g_cntV[gtid] = 0; g_fillV[gtid] = 0; }
        if (gtid < MM) { g_cntE[gtid] = 0; g_fillE[gtid] = 0; }
    }

    int w = tid >> 5, lane = tid & 31;
    int g = lane >> 2, q4 = lane & 3;
    int wr = w & 3, wc = w >> 2;
    int rowbase = blockIdx.x * 64;

    int lr0 = wr * 16 + g;
    int lr1 = lr0 + 8;
    int gr0 = min(rowbase + lr0, NN - 1);
    int gr1 = min(rowbase + lr1, NN - 1);

    float C[16][4];
#pragma unroll
    for (int nt = 0; nt < 16; nt++)
#pragma unroll
        for (int r = 0; r < 4; r++) C[nt][r] = 0.f;

    const unsigned* A0 = (const unsigned*)(g_Zn + (size_t)gr0 * DF);
    const unsigned* A1 = (const unsigned*)(g_Zn + (size_t)gr1 * DF);
#pragma unroll
    for (int ks = 0; ks < 8; ks++) {
        int ui = ks * 8 + q4;
        unsigned a0 = __ldg(&A0[ui]);
        unsigned a1 = __ldg(&A1[ui]);
        unsigned a2 = __ldg(&A0[ui + 4]);
        unsigned a3 = __ldg(&A1[ui + 4]);
#pragma unroll
        for (int nt = 0; nt < 16; nt++) {
            int n = wc * 128 + nt * 8 + g;
            const unsigned* Bp = (const unsigned*)(g_W1hT + (size_t)n * DF);
            unsigned b0 = __ldg(&Bp[ui]);
            unsigned b1 = __ldg(&Bp[ui + 4]);
            mma16816(C[nt], a0, a1, a2, a3, b0, b1);
        }
    }

    float s10 = g_invphi[STEPS] * (1.0f / 128.0f);   // descale Zn x128
    float f0 = s10 * g_sD[gr0];
    float f1 = s10 * g_sD[gr1];
    float s0 = 0.f, q0 = 0.f, s1 = 0.f, q1 = 0.f;
    float hb[16][4];
#pragma unroll
    for (int nt = 0; nt < 16; nt++) {
        int c = wc * 128 + nt * 8 + q4 * 2;
        float bb0 = __ldg(&b1v[c]);
        float bb1 = __ldg(&b1v[c + 1]);
        float h0 = C[nt][0] * f0 + bb0;
        float h1 = C[nt][1] * f0 + bb1;
        float h2 = C[nt][2] * f1 + bb0;
        float h3 = C[nt][3] * f1 + bb1;
        hb[nt][0] = h0; hb[nt][1] = h1; hb[nt][2] = h2; hb[nt][3] = h3;
        s0 += h0 + h1; q0 += h0 * h0 + h1 * h1;
        s1 += h2 + h3; q1 += h2 * h2 + h3 * h3;
    }
#pragma unroll
    for (int o = 1; o < 4; o <<= 1) {
        s0 += __shfl_xor_sync(0xffffffffu, s0, o);
        q0 += __shfl_xor_sync(0xffffffffu, q0, o);
        s1 += __shfl_xor_sync(0xffffffffu, s1, o);
        q1 += __shfl_xor_sync(0xffffffffu, q1, o);
    }
    if (q4 == 0) {
        red_s[wc][lr0] = s0; red_q[wc][lr0] = q0;
        red_s[wc][lr1] = s1; red_q[wc][lr1] = q1;
    }
    __syncthreads();
    float mu0, rs0, mu1, rs1;
    {
        float st = red_s[0][lr0] + red_s[1][lr0];
        float qt = red_q[0][lr0] + red_q[1][lr0];
        mu0 = st * (1.0f / 256.0f);
        rs0 = rsqrtf(qt * (1.0f / 256.0f) - mu0 * mu0 + 1e-5f);
        st = red_s[0][lr1] + red_s[1][lr1];
        qt = red_q[0][lr1] + red_q[1][lr1];
        mu1 = st * (1.0f / 256.0f);
        rs1 = rsqrtf(qt * (1.0f / 256.0f) - mu1 * mu1 + 1e-5f);
    }
#pragma unroll
    for (int nt = 0; nt < 16; nt++) {
        int c = wc * 128 + nt * 8 + q4 * 2;
        float gg0 = __ldg(&gammav[c]);
        float gg1 = __ldg(&gammav[c + 1]);
        float be0 = __ldg(&betav[c]);
        float be1 = __ldg(&betav[c + 1]);
        float h0 = fmaxf((hb[nt][0] - mu0) * rs0 * gg0 + be0, 0.f);
        float h1 = fmaxf((hb[nt][1] - mu0) * rs0 * gg1 + be1, 0.f);
        float h2 = fmaxf((hb[nt][2] - mu1) * rs1 * gg0 + be0, 0.f);
        float h3 = fmaxf((hb[nt][3] - mu1) * rs1 * gg1 + be1, 0.f);
        *(__half2*)&hs[lr0 * DPAD + c] = __floats2half2_rn(h0, h1);
        *(__half2*)&hs[lr1 * DPAD + c] = __floats2half2_rn(h2, h3);
    }
    __syncthreads();

    // phase 2 split across both warp-columns: wc=0 -> nt 0..2, wc=1 -> nt 3..4
    {
        int ntb = (wc == 0) ? 0 : 3;
        int ntn = (wc == 0) ? 3 : 2;
        float C2[3][4];
#pragma unroll
        for (int nt = 0; nt < 3; nt++)
#pragma unroll
            for (int r = 0; r < 4; r++) C2[nt][r] = 0.f;
#pragma unroll
        for (int ks = 0; ks < 16; ks++) {
            int k0 = ks * 16 + q4 * 2;
            unsigned a0 = *(unsigned*)&hs[lr0 * DPAD + k0];
            unsigned a1 = *(unsigned*)&hs[lr1 * DPAD + k0];
            unsigned a2 = *(unsigned*)&hs[lr0 * DPAD + k0 + 8];
            unsigned a3 = *(unsigned*)&hs[lr1 * DPAD + k0 + 8];
#pragma unroll
            for (int nt = 0; nt < 3; nt++) {
                if (nt < ntn) {
                    int n = (ntb + nt) * 8 + g;
                    const unsigned* Bp = (const unsigned*)(g_W2hT + (size_t)n * HIDN);
                    unsigned b0 = __ldg(&Bp[ks * 8 + q4]);
                    unsigned b1 = __ldg(&Bp[ks * 8 + q4 + 4]);
                    mma16816(C2[nt], a0, a1, a2, a3, b0, b1);
                }
            }
        }
        int row0 = rowbase + lr0;
        int row1 = rowbase + lr1;
#pragma unroll
        for (int nt = 0; nt < 3; nt++) {
            if (nt < ntn) {
                int c = (ntb + nt) * 8 + q4 * 2;
                float bb0 = __ldg(&b2v[c]);
                float bb1 = __ldg(&b2v[c + 1]);
                if (row0 < NN) {
                    float2 o = make_float2(C2[nt][0] + bb0, C2[nt][1] + bb1);
                    *(float2*)&out[(size_t)row0 * OUTC + c] = o;
                }
                if (row1 < NN) {
                    float2 o = make_float2(C2[nt][2] + bb0, C2[nt][3] + bb1);
                    *(float2*)&out[(size_t)row1 * OUTC + c] = o;
                }
            }
        }
    }
}

// ---------------- host ----------------
extern "C" void kernel_launch(void* const* d_in, const int* in_sizes, int n_in,
                              void* d_out, int out_size) {
    const float* x     = (const float*)d_in[0];
    const int*   hei   = (const int*)d_in[1];
    const float* W1    = (const float*)d_in[2];
    const float* b1    = (const float*)d_in[3];
    const float* gamma = (const float*)d_in[4];
    const float* beta  = (const float*)d_in[5];
    const float* W2    = (const float*)d_in[6];
    const float* b2    = (const float*)d_in[7];
    float* out = (float*)d_out;

    const int* V = hei;
    const int* E = hei + NNZT;

    __half* Xh;
    __half* Zn;
    cudaGetSymbolAddress((void**)&Xh, g_Xh);
    cudaGetSymbolAddress((void**)&Zn, g_Zn);

    // CSR build (counters pre-zeroed: static init first call, decoder prologue after)
    count_kernel<<<(NNZT + 255) / 256, 256>>>(V, E);
    convert_kernel<<<(NN * 32) / 256, 256>>>(x, W1, W2);   // invDE before sort's weight calc
    scan_fused<<<NBV, 256>>>();
    fill_kernel<<<(NNZT + 255) / 256, 256>>>(V, E);
    sort_both_kernel<<<EB + NB, 128>>>();   // also computes g_wV

    const int gridE_ = (MM * 32) / 256;   // 1250

    v2e_kernel<<<gridE_, 256>>>(Xh, 0);
    for (int t = 1; t < STEPS; t++) {
        e2v_kernel<<<EGRID, 256>>>(t);
        v2e_kernel<<<gridE_, 256>>>(Zn, t);
    }
    e2v_kernel<<<EGRID, 256>>>(STEPS);
    phi_node_kernel<<<PHIGRID, 256>>>(STEPS);

    decoder_kernel<<<(NN + 63) / 64, 256>>>(b1, gamma, beta, b2, out);
}

// round 16
// speedup vs baseline: 1.0012x; 1.0012x over previous
#include <cuda_runtime.h>
#include <cuda_fp16.h>
#include <math.h>

#define NN   50000
#define MM   10000
#define NNZT 400000
#define DF   128
#define HIDN 256
#define OUTC 40
#define STEPS 10

#define NBV 196                 // ceil(NN/256) == scan grid
#define NBE 40                  // ceil(MM/256)
#define EB  157                 // ceil(MM/64)  edge-sort blocks
#define NB  391                 // ceil(NN/128) node-sort blocks
#define FBLK 1563               // ceil(NNZT/256) fill blocks per side
#define EGRID  1184             // e2v exact-fit grid (148*8)
#define EWARPS (EGRID * 8)
#define PHIGRID 1024            // phi_node reduction grid

#define H2(x) (*(const __half2*)&(x))

// ---------------- scratch (static device globals; no allocation) ----------------
__device__ int   g_cntV[NN];
__device__ int   g_cntE[MM];
__device__ int   g_rowV[NN + 1];
__device__ int   g_rowE[MM + 1];
__device__ int   g_fillV[NN];
__device__ int   g_fillE[MM];
__device__ int   g_adjV[NNZT];
__device__ int   g_adjE[NNZT];
__device__ float g_invD[NN];
__device__ float g_sD[NN];
__device__ float g_wV[NN];             // sum_{e ∋ v} invDE[e]  (includes 1/16384)
__device__ float g_invDE[MM];          // pre-scaled by 1/16384 (features stored x128)
__device__ __align__(16) __half g_Xh[(size_t)NN * DF];   // 128 * X / sqrtD (fp16)
__device__ __align__(16) __half g_Zn[(size_t)NN * DF];   // 128 * G / sqrtD (fp16)
__device__ __align__(16) __half g_Pe[(size_t)MM * DF];   // V2E(G), unscaled (fp16)
__device__ __align__(16) __half g_W1hT[(size_t)HIDN * DF];   // W1^T fp16
__device__ __align__(16) __half g_W2hT[(size_t)OUTC * HIDN]; // W2^T fp16
__device__ float g_part[2048];
__device__ int   g_arrive;
__device__ float g_invphi[STEPS + 1];
__device__ int   g_scanPartV[256];
__device__ int   g_scanPartE[256];
__device__ int          g_fbarCnt;
__device__ volatile int g_fbarGen;

// ---------------- CSR build ----------------
__global__ void count_kernel(const int* __restrict__ V, const int* __restrict__ E) {
    int i = blockIdx.x * blockDim.x + threadIdx.x;
    if (i >= NNZT) return;
    atomicAdd(&g_cntV[V[i]], 1);
    atomicAdd(&g_cntE[E[i]], 1);
}

// Fused 3-phase scan: block partials -> ONE grid barrier -> rowptr write
__global__ void __launch_bounds__(256) scan_fused() {
    __shared__ int ss[256];
    __shared__ int sbase;
    int tid = threadIdx.x;
    int b = blockIdx.x;

    {
        int i = b * 256 + tid;
        ss[tid] = (i < NN) ? g_cntV[i] : 0;
        __syncthreads();
        for (int o = 128; o; o >>= 1) {
            if (tid < o) ss[tid] += ss[tid + o];
            __syncthreads();
        }
        if (tid == 0) g_scanPartV[b] = ss[0];
        __syncthreads();
        if (b < NBE) {
            int j = b * 256 + tid;
            ss[tid] = (j < MM) ? g_cntE[j] : 0;
            __syncthreads();
            for (int o = 128; o; o >>= 1) {
                if (tid < o) ss[tid] += ss[tid + o];
                __syncthreads();
            }
            if (tid == 0) g_scanPartE[b] = ss[0];
            __syncthreads();
        }
    }
    __syncthreads();
    if (tid == 0) {
        __threadfence();
        int gen = g_fbarGen;
        if (atomicAdd(&g_fbarCnt, 1) == NBV - 1) {
            g_fbarCnt = 0;
            __threadfence();
            g_fbarGen = gen + 1;
        } else {
            while (g_fbarGen == gen) { __nanosleep(32); }
            __threadfence();
        }
    }
    __syncthreads();
    {
        int x = (tid < NBV) ? __ldcg(&g_scanPartV[tid]) : 0;
        ss[tid] = x;
        __syncthreads();
        for (int o = 1; o < 256; o <<= 1) {
            int u = 0;
            if (tid >= o) u = ss[tid - o];
            __syncthreads();
            ss[tid] += u;
            __syncthreads();
        }
        if (tid == 0) sbase = (b == 0) ? 0 : ss[b - 1];
        __syncthreads();
        int baseV = sbase;
        __syncthreads();
        int i = b * 256 + tid;
        int v = (i < NN) ? g_cntV[i] : 0;
        ss[tid] = v;
        __syncthreads();
        for (int o = 1; o < 256; o <<= 1) {
            int u = 0;
            if (tid >= o) u = ss[tid - o];
            __syncthreads();
            ss[tid] += u;
            __syncthreads();
        }
        if (i < NN) {
            g_rowV[i] = baseV + ss[tid] - v;
            if (i == NN - 1) g_rowV[NN] = baseV + ss[tid];
        }
        __syncthreads();
        if (b < NBE) {
            int x2 = (tid < NBE) ? __ldcg(&g_scanPartE[tid]) : 0;
            ss[tid] = x2;
            __syncthreads();
            for (int o = 1; o < 256; o <<= 1) {
                int u = 0;
                if (tid >= o) u = ss[tid - o];
                __syncthreads();
                ss[tid] += u;
                __syncthreads();
            }
            if (tid == 0) sbase = (b == 0) ? 0 : ss[b - 1];
            __syncthreads();
            int baseE = sbase;
            int j = b * 256 + tid;
            int e = (j < MM) ? g_cntE[j] : 0;
            ss[tid] = e;
            __syncthreads();
            for (int o = 1; o < 256; o <<= 1) {
                int u = 0;
                if (tid >= o) u = ss[tid - o];
                __syncthreads();
                ss[tid] += u;
                __syncthreads();
            }
            if (j < MM) {
                g_rowE[j] = baseE + ss[tid] - e;
                if (j == MM - 1) g_rowE[MM] = baseE + ss[tid];
            }
        }
    }
}

// Split fill: first FBLK blocks do the V-side chain, next FBLK do the E-side.
// Single atomic->store chain per thread (2x parallelism, half the latency chain).
// Fill order differs from before, but canonical sort makes adjacency identical.
__global__ void fill_kernel(const int* __restrict__ V, const int* __restrict__ E) {
    int b = blockIdx.x;
    if (b < FBLK) {
        int i = b * 256 + threadIdx.x;
        if (i >= NNZT) return;
        int v = V[i];
        int pv = g_rowV[v] + atomicAdd(&g_fillV[v], 1);
        g_adjV[pv] = E[i];
    } else {
        int i = (b - FBLK) * 256 + threadIdx.x;
        if (i >= NNZT) return;
        int e = E[i];
        int pe = g_rowE[e] + atomicAdd(&g_fillE[e], 1);
        g_adjE[pe] = V[i];
    }
}

// Both segment sorts (edges then nodes) in one launch; insertion sort in smem.
// Node path also computes g_wV (sum of invDE over sorted adjacency, fixed order).
__global__ void sort_both_kernel() {
    __shared__ int buf[8192];
    int t = threadIdx.x;
    if (blockIdx.x < EB) {
        if (t >= 64) return;
        int sgi = blockIdx.x * 64 + t;
        if (sgi >= MM) return;
        int s = g_rowE[sgi], e = g_rowE[sgi + 1];
        int len = e - s;
        if (len <= 1) return;
        if (len <= 128) {
            for (int k = 0; k < len; k++) buf[t + 64 * k] = g_adjE[s + k];
            for (int i = 1; i < len; i++) {
                int key = buf[t + 64 * i];
                int j = i - 1;
                while (j >= 0 && buf[t + 64 * j] > key) {
                    buf[t + 64 * (j + 1)] = buf[t + 64 * j];
                    j--;
                }
                buf[t + 64 * (j + 1)] = key;
            }
            for (int k = 0; k < len; k++) g_adjE[s + k] = buf[t + 64 * k];
        } else {
            for (int i = s + 1; i < e; i++) {
                int key = g_adjE[i];
                int j = i - 1;
                while (j >= s && g_adjE[j] > key) { g_adjE[j + 1] = g_adjE[j]; j--; }
                g_adjE[j + 1] = key;
            }
        }
    } else {
        int sgi = (blockIdx.x - EB) * 128 + t;
        if (sgi >= NN) return;
        int s = g_rowV[sgi], e = g_rowV[sgi + 1];
        int len = e - s;
        float w = 0.f;
        if (len <= 1) {
            if (len == 1) w = __ldg(&g_invDE[g_adjV[s]]);
            g_wV[sgi] = w;
            return;
        }
        if (len <= 48) {
            for (int k = 0; k < len; k++) buf[t + 128 * k] = g_adjV[s + k];
            for (int i = 1; i < len; i++) {
                int key = buf[t + 128 * i];
                int j = i - 1;
                while (j >= 0 && buf[t + 128 * j] > key) {
                    buf[t + 128 * (j + 1)] = buf[t + 128 * j];
                    j--;
                }
                buf[t + 128 * (j + 1)] = key;
            }
            for (int k = 0; k < len; k++) {
                int a = buf[t + 128 * k];
                g_adjV[s + k] = a;
                w += __ldg(&g_invDE[a]);
            }
        } else {
            for (int i = s + 1; i < e; i++) {
                int key = g_adjV[i];
                int j = i - 1;
                while (j >= s && g_adjV[j] > key) { g_adjV[j + 1] = g_adjV[j]; j--; }
                g_adjV[j + 1] = key;
            }
            for (int k = 0; k < len; k++) w += __ldg(&g_invDE[g_adjV[s + k]]);
        }
        g_wV[sgi] = w;
    }
}

// Xh = 128 * X * rsD (fp16); scalars (invDE pre-divided by 16384); W fp16.
__global__ void convert_kernel(const float* __restrict__ X,
                               const float* __restrict__ W1,
                               const float* __restrict__ W2) {
    int i = blockIdx.x * blockDim.x + threadIdx.x;  // over NN*32
    int row = i >> 5;
    float c = (float)__ldg(&g_cntV[row]);
    float r = rsqrtf(c) * 128.0f;
    float4 x = __ldg(&((const float4*)X)[i]);
    __half2 h0 = __floats2half2_rn(x.x * r, x.y * r);
    __half2 h1 = __floats2half2_rn(x.z * r, x.w * r);
    uint2 u;
    u.x = *(unsigned*)&h0;
    u.y = *(unsigned*)&h1;
    ((uint2*)g_Xh)[i] = u;
    if (i < NN) {
        float cv = (float)g_cntV[i];
        g_invD[i] = 1.0f / cv;
        g_sD[i] = sqrtf(cv);
    }
    if (i < MM) {
        g_invDE[i] = 1.0f / (16384.0f * (float)g_cntE[i]);
    }
    if (i < HIDN * DF) {
        int n = i >> 7, k = i & 127;
        g_W1hT[i] = __float2half(__ldg(&W1[k * HIDN + n]));
    }
    if (i < OUTC * HIDN) {
        int n = i >> 8, k = i & 255;
        g_W2hT[i] = __float2half(__ldg(&W2[k * OUTC + n]));
    }
}

// ---------------- diffusion ----------------
__device__ __forceinline__ void acc_sq(float* a, uint4 u) {
    float2 a0 = __half22float2(H2(u.x));
    float2 a1 = __half22float2(H2(u.y));
    float2 a2 = __half22float2(H2(u.z));
    float2 a3 = __half22float2(H2(u.w));
    a[0] += a0.x * a0.x; a[1] += a0.y * a0.y;
    a[2] += a1.x * a1.x; a[3] += a1.y * a1.y;
    a[4] += a2.x * a2.x; a[5] += a2.y * a2.y;
    a[6] += a3.x * a3.x; a[7] += a3.y * a3.y;
}
__device__ __forceinline__ void acc_lin(float* a, uint4 u) {
    float2 a0 = __half22float2(H2(u.x));
    float2 a1 = __half22float2(H2(u.y));
    float2 a2 = __half22float2(H2(u.z));
    float2 a3 = __half22float2(H2(u.w));
    a[0] += a0.x; a[1] += a0.y; a[2] += a1.x; a[3] += a1.y;
    a[4] += a2.x; a[5] += a2.y; a[6] += a3.x; a[7] += a3.y;
}
__device__ __forceinline__ void hacc_sq(__half2& hx, __half2& hy, __half2& hz, __half2& hw,
                                        uint4 u) {
    hx = __hfma2(H2(u.x), H2(u.x), hx);
    hy = __hfma2(H2(u.y), H2(u.y), hy);
    hz = __hfma2(H2(u.z), H2(u.z), hz);
    hw = __hfma2(H2(u.w), H2(u.w), hw);
}
__device__ __forceinline__ void flush4(float* acc, __half2 hx, __half2 hy, __half2 hz, __half2 hw) {
    float2 f;
    f = __half22float2(hx); acc[0] += f.x; acc[1] += f.y;
    f = __half22float2(hy); acc[2] += f.x; acc[3] += f.y;
    f = __half22float2(hz); acc[4] += f.x; acc[5] += f.y;
    f = __half22float2(hw); acc[6] += f.x; acc[7] += f.y;
}

// V2E + phi fused. Warp per hyperedge; half-warps split incidences (stride 2).
__global__ void v2e_kernel(const __half* __restrict__ Z, int t) {
    int warp = (blockIdx.x * blockDim.x + threadIdx.x) >> 5;
    int lane = threadIdx.x & 31;
    int half = lane >> 4;
    int fl = lane & 15;
    float ps = 0.f;
    if (warp < MM) {
        int e = warp;
        int s = g_rowE[e], en = g_rowE[e + 1];
        const uint4* Z4 = (const uint4*)Z;
        float acc[8];
#pragma unroll
        for (int k = 0; k < 8; k++) acc[k] = 0.f;
        int j = s + half;
        for (; j + 6 < en; j += 8) {
            int v0 = __ldg(&g_adjE[j]);
            int v1 = __ldg(&g_adjE[j + 2]);
            int v2i = __ldg(&g_adjE[j + 4]);
            int v3 = __ldg(&g_adjE[j + 6]);
            uint4 u0 = __ldg(&Z4[(size_t)v0 * 16 + fl]);
            uint4 u1 = __ldg(&Z4[(size_t)v1 * 16 + fl]);
            uint4 u2 = __ldg(&Z4[(size_t)v2i * 16 + fl]);
            uint4 u3 = __ldg(&Z4[(size_t)v3 * 16 + fl]);
            __half2 hx = __hmul2(H2(u0.x), H2(u0.x));
            __half2 hy = __hmul2(H2(u0.y), H2(u0.y));
            __half2 hz = __hmul2(H2(u0.z), H2(u0.z));
            __half2 hw = __hmul2(H2(u0.w), H2(u0.w));
            hacc_sq(hx, hy, hz, hw, u1);
            hacc_sq(hx, hy, hz, hw, u2);
            hacc_sq(hx, hy, hz, hw, u3);
            flush4(acc, hx, hy, hz, hw);
        }
        for (; j + 2 < en; j += 4) {
            int v0 = __ldg(&g_adjE[j]);
            int v1 = __ldg(&g_adjE[j + 2]);
            uint4 u0 = __ldg(&Z4[(size_t)v0 * 16 + fl]);
            uint4 u1 = __ldg(&Z4[(size_t)v1 * 16 + fl]);
            __half2 hx = __hmul2(H2(u0.x), H2(u0.x));
            __half2 hy = __hmul2(H2(u0.y), H2(u0.y));
            __half2 hz = __hmul2(H2(u0.z), H2(u0.z));
            __half2 hw = __hmul2(H2(u0.w), H2(u0.w));
            hacc_sq(hx, hy, hz, hw, u1);
            flush4(acc, hx, hy, hz, hw);
        }
        for (; j < en; j += 2) {
            int v = __ldg(&g_adjE[j]);
            uint4 u = __ldg(&Z4[(size_t)v * 16 + fl]);
            acc_sq(acc, u);
        }
#pragma unroll
        for (int k = 0; k < 8; k++) acc[k] += __shfl_xor_sync(0xffffffffu, acc[k], 16);
        if (half == 0) {
            float ide = g_invDE[e];
            float v0 = acc[0] * ide, v1 = acc[1] * ide, v2 = acc[2] * ide, v3 = acc[3] * ide;
            float v4 = acc[4] * ide, v5 = acc[5] * ide, v6 = acc[6] * ide, v7 = acc[7] * ide;
            __half2 o0 = __floats2half2_rn(sqrtf(v0), sqrtf(v1));
            __half2 o1 = __floats2half2_rn(sqrtf(v2), sqrtf(v3));
            __half2 o2 = __floats2half2_rn(sqrtf(v4), sqrtf(v5));
            __half2 o3 = __floats2half2_rn(sqrtf(v6), sqrtf(v7));
            uint4 u;
            u.x = *(unsigned*)&o0; u.y = *(unsigned*)&o1;
            u.z = *(unsigned*)&o2; u.w = *(unsigned*)&o3;
            ((uint4*)g_Pe)[(size_t)e * 16 + fl] = u;
            ps = v0 + v1 + v2 + v3 + v4 + v5 + v6 + v7;
        }
    }
#pragma unroll
    for (int o = 16; o; o >>= 1) ps += __shfl_xor_sync(0xffffffffu, ps, o);

    __shared__ float wsum[8];
    __shared__ int lastflag;
    if (lane == 0) wsum[threadIdx.x >> 5] = ps;
    __syncthreads();
    if (threadIdx.x == 0) {
        float b = 0.f;
#pragma unroll
        for (int w = 0; w < 8; w++) b += wsum[w];
        g_part[blockIdx.x] = b;
        __threadfence();
        int old = atomicAdd(&g_arrive, 1);
        lastflag = (old == (int)gridDim.x - 1);
    }
    __syncthreads();
    if (lastflag) {
        __threadfence();
        float sacc = 0.f;
        for (int i = threadIdx.x; i < (int)gridDim.x; i += 256) sacc += g_part[i];
        __shared__ float sr[256];
        sr[threadIdx.x] = sacc;
        __syncthreads();
        for (int o = 128; o; o >>= 1) {
            if (threadIdx.x < o) sr[threadIdx.x] += sr[threadIdx.x + o];
            __syncthreads();
        }
        if (threadIdx.x == 0) {
            g_invphi[t] = 1.0f / (2.0f * sqrtf(sr[0]));
            g_arrive = 0;
        }
    }
}

// E2V + combine. Exact-fit grid (1 wave @8/SM), block-stride over nodes.
__global__ void __launch_bounds__(256) e2v_kernel(int t) {
    int gwarp = (blockIdx.x * blockDim.x + threadIdx.x) >> 5;
    int lane = threadIdx.x & 31;
    int half = lane >> 4;
    int fl = lane & 15;
    float sp = g_invphi[t - 1];
    float s0 = g_invphi[0];
    const uint4* Pe4 = (const uint4*)g_Pe;
    for (int v = gwarp; v < NN; v += EWARPS) {
        int s = g_rowV[v], en = g_rowV[v + 1];
        float acc[8];
#pragma unroll
        for (int k = 0; k < 8; k++) acc[k] = 0.f;
        int j = s + half;
        for (; j + 6 < en; j += 8) {
            int e0 = __ldg(&g_adjV[j]);
            int e1 = __ldg(&g_adjV[j + 2]);
            int e2 = __ldg(&g_adjV[j + 4]);
            int e3 = __ldg(&g_adjV[j + 6]);
            uint4 u0 = __ldg(&Pe4[(size_t)e0 * 16 + fl]);
            uint4 u1 = __ldg(&Pe4[(size_t)e1 * 16 + fl]);
            uint4 u2 = __ldg(&Pe4[(size_t)e2 * 16 + fl]);
            uint4 u3 = __ldg(&Pe4[(size_t)e3 * 16 + fl]);
            __half2 hx = __hadd2(__hadd2(H2(u0.x), H2(u1.x)), __hadd2(H2(u2.x), H2(u3.x)));
            __half2 hy = __hadd2(__hadd2(H2(u0.y), H2(u1.y)), __hadd2(H2(u2.y), H2(u3.y)));
            __half2 hz = __hadd2(__hadd2(H2(u0.z), H2(u1.z)), __hadd2(H2(u2.z), H2(u3.z)));
            __half2 hw = __hadd2(__hadd2(H2(u0.w), H2(u1.w)), __hadd2(H2(u2.w), H2(u3.w)));
            flush4(acc, hx, hy, hz, hw);
        }
        for (; j + 2 < en; j += 4) {
            int e0 = __ldg(&g_adjV[j]);
            int e1 = __ldg(&g_adjV[j + 2]);
            uint4 u0 = __ldg(&Pe4[(size_t)e0 * 16 + fl]);
            uint4 u1 = __ldg(&Pe4[(size_t)e1 * 16 + fl]);
            __half2 hx = __hadd2(H2(u0.x), H2(u1.x));
            __half2 hy = __hadd2(H2(u0.y), H2(u1.y));
            __half2 hz = __hadd2(H2(u0.z), H2(u1.z));
            __half2 hw = __hadd2(H2(u0.w), H2(u1.w));
            flush4(acc, hx, hy, hz, hw);
        }
        for (; j < en; j += 2) {
            int e = __ldg(&g_adjV[j]);
            uint4 u = __ldg(&Pe4[(size_t)e * 16 + fl]);
            acc_lin(acc, u);
        }
#pragma unroll
        for (int k = 0; k < 8; k++) acc[k] += __shfl_xor_sync(0xffffffffu, acc[k], 16);
        if (half == 0) {
            float a = 115.2f * sp * g_invD[v];
            float b = 0.1f * s0;
            uint4 ux = __ldg(&((const uint4*)g_Xh)[(size_t)v * 16 + fl]);
            float2 x0 = __half22float2(H2(ux.x));
            float2 x1 = __half22float2(H2(ux.y));
            float2 x2 = __half22float2(H2(ux.z));
            float2 x3 = __half22float2(H2(ux.w));
            __half2 o0 = __floats2half2_rn(a * acc[0] + b * x0.x, a * acc[1] + b * x0.y);
            __half2 o1 = __floats2half2_rn(a * acc[2] + b * x1.x, a * acc[3] + b * x1.y);
            __half2 o2 = __floats2half2_rn(a * acc[4] + b * x2.x, a * acc[5] + b * x2.y);
            __half2 o3 = __floats2half2_rn(a * acc[6] + b * x3.x, a * acc[7] + b * x3.y);
            uint4 u;
            u.x = *(unsigned*)&o0; u.y = *(unsigned*)&o1;
            u.z = *(unsigned*)&o2; u.w = *(unsigned*)&o3;
            ((uint4*)g_Zn)[(size_t)v * 16 + fl] = u;
        }
    }
}

// Final phi via node identity: S = sum_v w_v * ||Zn_v||^2 (w includes 1/16384).
__global__ void __launch_bounds__(256) phi_node_kernel(int t) {
    const uint2* Z2 = (const uint2*)g_Zn;
    int tid = threadIdx.x;
    int stride = PHIGRID * 256;
    float s = 0.f;
    for (int i = blockIdx.x * 256 + tid; i < NN * 32; i += stride) {
        float w = __ldg(&g_wV[i >> 5]);
        uint2 u = __ldg(&Z2[i]);
        float2 a0 = __half22float2(H2(u.x));
        float2 a1 = __half22float2(H2(u.y));
        s += w * (a0.x * a0.x + a0.y * a0.y + a1.x * a1.x + a1.y * a1.y);
    }
    __shared__ float sr[256];
    __shared__ int lastflag;
    sr[tid] = s;
    __syncthreads();
    for (int o = 128; o; o >>= 1) {
        if (tid < o) sr[tid] += sr[tid + o];
        __syncthreads();
    }
    if (tid == 0) {
        g_part[blockIdx.x] = sr[0];
        __threadfence();
        int old = atomicAdd(&g_arrive, 1);
        lastflag = (old == PHIGRID - 1);
    }
    __syncthreads();
    if (lastflag) {
        __threadfence();
        float sacc = 0.f;
        for (int i = tid; i < PHIGRID; i += 256) sacc += g_part[i];
        sr[tid] = sacc;
        __syncthreads();
        for (int o = 128; o; o >>= 1) {
            if (tid < o) sr[tid] += sr[tid + o];
            __syncthreads();
        }
        if (tid == 0) {
            g_invphi[t] = 1.0f / (2.0f * sqrtf(sr[0]));
            g_arrive = 0;
        }
    }
}

// ---------------- tensor-core decoder ----------------
__device__ __forceinline__ void mma16816(float* c, unsigned a0, unsigned a1, unsigned a2,
                                         unsigned a3, unsigned b0, unsigned b1) {
    asm volatile(
        "mma.sync.aligned.m16n8k16.row.col.f32.f16.f16.f32 "
        "{%0,%1,%2,%3}, {%4,%5,%6,%7}, {%8,%9}, {%0,%1,%2,%3};"
        : "+f"(c[0]), "+f"(c[1]), "+f"(c[2]), "+f"(c[3])
        : "r"(a0), "r"(a1), "r"(a2), "r"(a3), "r"(b0), "r"(b1));
}

#define DPAD 264
__global__ void decoder_kernel(const float* __restrict__ b1v, const float* __restrict__ gammav,
                               const float* __restrict__ betav, const float* __restrict__ b2v,
                               float* __restrict__ out) {
    __shared__ __half hs[64 * DPAD];
    __shared__ float red_s[2][64];
    __shared__ float red_q[2][64];

    int tid = threadIdx.x;

    // re-zero CSR counters for the next graph replay (first run: static zero-init)
    {
        int gtid = blockIdx.x * 256 + tid;
        if (gtid < NN) { g_cntV[gtid] = 0; g_fillV[gtid] = 0; }
        if (gtid < MM) { g_cntE[gtid] = 0; g_fillE[gtid] = 0; }
    }

    int w = tid >> 5, lane = tid & 31;
    int g = lane >> 2, q4 = lane & 3;
    int wr = w & 3, wc = w >> 2;
    int rowbase = blockIdx.x * 64;

    int lr0 = wr * 16 + g;
    int lr1 = lr0 + 8;
    int gr0 = min(rowbase + lr0, NN - 1);
    int gr1 = min(rowbase + lr1, NN - 1);

    float C[16][4];
#pragma unroll
    for (int nt = 0; nt < 16; nt++)
#pragma unroll
        for (int r = 0; r < 4; r++) C[nt][r] = 0.f;

    const unsigned* A0 = (const unsigned*)(g_Zn + (size_t)gr0 * DF);
    const unsigned* A1 = (const unsigned*)(g_Zn + (size_t)gr1 * DF);
#pragma unroll
    for (int ks = 0; ks < 8; ks++) {
        int ui = ks * 8 + q4;
        unsigned a0 = __ldg(&A0[ui]);
        unsigned a1 = __ldg(&A1[ui]);
        unsigned a2 = __ldg(&A0[ui + 4]);
        unsigned a3 = __ldg(&A1[ui + 4]);
#pragma unroll
        for (int nt = 0; nt < 16; nt++) {
            int n = wc * 128 + nt * 8 + g;
            const unsigned* Bp = (const unsigned*)(g_W1hT + (size_t)n * DF);
            unsigned b0 = __ldg(&Bp[ui]);
            unsigned b1 = __ldg(&Bp[ui + 4]);
            mma16816(C[nt], a0, a1, a2, a3, b0, b1);
        }
    }

    float s10 = g_invphi[STEPS] * (1.0f / 128.0f);   // descale Zn x128
    float f0 = s10 * g_sD[gr0];
    float f1 = s10 * g_sD[gr1];
    float s0 = 0.f, q0 = 0.f, s1 = 0.f, q1 = 0.f;
    float hb[16][4];
#pragma unroll
    for (int nt = 0; nt < 16; nt++) {
        int c = wc * 128 + nt * 8 + q4 * 2;
        float bb0 = __ldg(&b1v[c]);
        float bb1 = __ldg(&b1v[c + 1]);
        float h0 = C[nt][0] * f0 + bb0;
        float h1 = C[nt][1] * f0 + bb1;
        float h2 = C[nt][2] * f1 + bb0;
        float h3 = C[nt][3] * f1 + bb1;
        hb[nt][0] = h0; hb[nt][1] = h1; hb[nt][2] = h2; hb[nt][3] = h3;
        s0 += h0 + h1; q0 += h0 * h0 + h1 * h1;
        s1 += h2 + h3; q1 += h2 * h2 + h3 * h3;
    }
#pragma unroll
    for (int o = 1; o < 4; o <<= 1) {
        s0 += __shfl_xor_sync(0xffffffffu, s0, o);
        q0 += __shfl_xor_sync(0xffffffffu, q0, o);
        s1 += __shfl_xor_sync(0xffffffffu, s1, o);
        q1 += __shfl_xor_sync(0xffffffffu, q1, o);
    }
    if (q4 == 0) {
        red_s[wc][lr0] = s0; red_q[wc][lr0] = q0;
        red_s[wc][lr1] = s1; red_q[wc][lr1] = q1;
    }
    __syncthreads();
    float mu0, rs0, mu1, rs1;
    {
        float st = red_s[0][lr0] + red_s[1][lr0];
        float qt = red_q[0][lr0] + red_q[1][lr0];
        mu0 = st * (1.0f / 256.0f);
        rs0 = rsqrtf(qt * (1.0f / 256.0f) - mu0 * mu0 + 1e-5f);
        st = red_s[0][lr1] + red_s[1][lr1];
        qt = red_q[0][lr1] + red_q[1][lr1];
        mu1 = st * (1.0f / 256.0f);
        rs1 = rsqrtf(qt * (1.0f / 256.0f) - mu1 * mu1 + 1e-5f);
    }
#pragma unroll
    for (int nt = 0; nt < 16; nt++) {
        int c = wc * 128 + nt * 8 + q4 * 2;
        float gg0 = __ldg(&gammav[c]);
        float gg1 = __ldg(&gammav[c + 1]);
        float be0 = __ldg(&betav[c]);
        float be1 = __ldg(&betav[c + 1]);
        float h0 = fmaxf((hb[nt][0] - mu0) * rs0 * gg0 + be0, 0.f);
        float h1 = fmaxf((hb[nt][1] - mu0) * rs0 * gg1 + be1, 0.f);
        float h2 = fmaxf((hb[nt][2] - mu1) * rs1 * gg0 + be0, 0.f);
        float h3 = fmaxf((hb[nt][3] - mu1) * rs1 * gg1 + be1, 0.f);
        *(__half2*)&hs[lr0 * DPAD + c] = __floats2half2_rn(h0, h1);
        *(__half2*)&hs[lr1 * DPAD + c] = __floats2half2_rn(h2, h3);
    }
    __syncthreads();

    // phase 2 split across both warp-columns: wc=0 -> nt 0..2, wc=1 -> nt 3..4
    {
        int ntb = (wc == 0) ? 0 : 3;
        int ntn = (wc == 0) ? 3 : 2;
        float C2[3][4];
#pragma unroll
        for (int nt = 0; nt < 3; nt++)
#pragma unroll
            for (int r = 0; r < 4; r++) C2[nt][r] = 0.f;
#pragma unroll
        for (int ks = 0; ks < 16; ks++) {
            int k0 = ks * 16 + q4 * 2;
            unsigned a0 = *(unsigned*)&hs[lr0 * DPAD + k0];
            unsigned a1 = *(unsigned*)&hs[lr1 * DPAD + k0];
            unsigned a2 = *(unsigned*)&hs[lr0 * DPAD + k0 + 8];
            unsigned a3 = *(unsigned*)&hs[lr1 * DPAD + k0 + 8];
#pragma unroll
            for (int nt = 0; nt < 3; nt++) {
                if (nt < ntn) {
                    int n = (ntb + nt) * 8 + g;
                    const unsigned* Bp = (const unsigned*)(g_W2hT + (size_t)n * HIDN);
                    unsigned b0 = __ldg(&Bp[ks * 8 + q4]);
                    unsigned b1 = __ldg(&Bp[ks * 8 + q4 + 4]);
                    mma16816(C2[nt], a0, a1, a2, a3, b0, b1);
                }
            }
        }
        int row0 = rowbase + lr0;
        int row1 = rowbase + lr1;
#pragma unroll
        for (int nt = 0; nt < 3; nt++) {
            if (nt < ntn) {
                int c = (ntb + nt) * 8 + q4 * 2;
                float bb0 = __ldg(&b2v[c]);
                float bb1 = __ldg(&b2v[c + 1]);
                if (row0 < NN) {
                    float2 o = make_float2(C2[nt][0] + bb0, C2[nt][1] + bb1);
                    *(float2*)&out[(size_t)row0 * OUTC + c] = o;
                }
                if (row1 < NN) {
                    float2 o = make_float2(C2[nt][2] + bb0, C2[nt][3] + bb1);
                    *(float2*)&out[(size_t)row1 * OUTC + c] = o;
                }
            }
        }
    }
}

// ---------------- host ----------------
extern "C" void kernel_launch(void* const* d_in, const int* in_sizes, int n_in,
                              void* d_out, int out_size) {
    const float* x     = (const float*)d_in[0];
    const int*   hei   = (const int*)d_in[1];
    const float* W1    = (const float*)d_in[2];
    const float* b1    = (const float*)d_in[3];
    const float* gamma = (const float*)d_in[4];
    const float* beta  = (const float*)d_in[5];
    const float* W2    = (const float*)d_in[6];
    const float* b2    = (const float*)d_in[7];
    float* out = (float*)d_out;

    const int* V = hei;
    const int* E = hei + NNZT;

    __half* Xh;
    __half* Zn;
    cudaGetSymbolAddress((void**)&Xh, g_Xh);
    cudaGetSymbolAddress((void**)&Zn, g_Zn);

    // CSR build (counters pre-zeroed: static init first call, decoder prologue after)
    count_kernel<<<(NNZT + 255) / 256, 256>>>(V, E);
    convert_kernel<<<(NN * 32) / 256, 256>>>(x, W1, W2);
    scan_fused<<<NBV, 256>>>();
    fill_kernel<<<2 * FBLK, 256>>>(V, E);   // split V-side / E-side halves
    sort_both_kernel<<<EB + NB, 128>>>();

    const int gridE_ = (MM * 32) / 256;   // 1250

    v2e_kernel<<<gridE_, 256>>>(Xh, 0);
    for (int t = 1; t < STEPS; t++) {
        e2v_kernel<<<EGRID, 256>>>(t);
        v2e_kernel<<<gridE_, 256>>>(Zn, t);
    }
    e2v_kernel<<<EGRID, 256>>>(STEPS);
    phi_node_kernel<<<PHIGRID, 256>>>(STEPS);

    decoder_kernel<<<(NN + 63) / 64, 256>>>(b1, gamma, beta, b2, out);
}